// round 10
// baseline (speedup 1.0000x reference)
#include <cuda_runtime.h>

#define BB 128
#define SS 48
#define DD 8
#define HDD 8
#define LL 8
#define NCLS 7
#define NTOT (BB*SS*SS*DD)   // 2,359,296 floats = 9.4 MB

// Static scratch. Layout convention:
//   g_h0  [b][i][j][d]   (row-major over (i,j))
//   g_h0T [b][j][i][d]   (transposed copy for axis-0 coalescing)
//   g_col [b][i][j][d]   (axis-1 outputs, own-layout)
//   g_row [b][j][i][d]   (axis-0 outputs, TRANSPOSED own-layout)
__device__ float g_h0[NTOT];
__device__ float g_h0T[NTOT];
__device__ float g_row[2][NTOT];
__device__ float g_col[2][NTOT];

// ---------------- f32x2 packed-math helpers (Blackwell) ----------------
__device__ __forceinline__ float2 mk2(float a, float b) { return make_float2(a, b); }

__device__ __forceinline__ float2 mul2(float2 a, float2 b) {
    float2 r;
    asm("mul.rn.f32x2 %0, %1, %2;"
        : "=l"(reinterpret_cast<unsigned long long&>(r))
        : "l"(reinterpret_cast<const unsigned long long&>(a)),
          "l"(reinterpret_cast<const unsigned long long&>(b)));
    return r;
}
__device__ __forceinline__ float2 fma2(float2 a, float2 b, float2 c) {
    float2 r;
    asm("fma.rn.f32x2 %0, %1, %2, %3;"
        : "=l"(reinterpret_cast<unsigned long long&>(r))
        : "l"(reinterpret_cast<const unsigned long long&>(a)),
          "l"(reinterpret_cast<const unsigned long long&>(b)),
          "l"(reinterpret_cast<const unsigned long long&>(c)));
    return r;
}
__device__ __forceinline__ float ex2f(float x) {
    float r; asm("ex2.approx.f32 %0, %1;" : "=f"(r) : "f"(x)); return r;
}

// ---------------------------------------------------------------------------
// Encoder: writes both layouts so layer 0 reads coalesced on both axes.
// ---------------------------------------------------------------------------
__global__ __launch_bounds__(256) void encoder_kernel(
    const float* __restrict__ x,
    const float* __restrict__ enc_w,
    const float* __restrict__ enc_b,
    const float* __restrict__ pos_row,
    const float* __restrict__ pos_col)
{
    int idx = blockIdx.x * blockDim.x + threadIdx.x;   // (b,i,j)
    if (idx >= BB * SS * SS) return;
    int j = idx % SS;
    int i = (idx / SS) % SS;
    int b = idx / (SS * SS);
    float xv = x[idx];
    float out[8];
#pragma unroll
    for (int d = 0; d < 8; d++) {
        float v = fmaxf(fmaf(xv, enc_w[d], enc_b[d]), 0.f);
        out[d] = v + pos_row[i * DD + d] + pos_col[j * DD + d];
    }
    float4 lo = make_float4(out[0], out[1], out[2], out[3]);
    float4 hi = make_float4(out[4], out[5], out[6], out[7]);
    float4* dst = (float4*)&g_h0[(size_t)idx * 8];
    dst[0] = lo; dst[1] = hi;
    float4* dstT = (float4*)&g_h0T[((size_t)(b * SS + j) * SS + i) * 8];
    dstT[0] = lo; dstT[1] = hi;
}

// ---------------------------------------------------------------------------
// One axial self-attention block.  blockIdx = (slice, batch, axis).
// In its OWN layout every block sees tokens at [b][slice][tok][d] -> fully
// coalesced loads and stores.  Only the cross-array combine load is scattered.
// ---------------------------------------------------------------------------
__global__ __launch_bounds__(96, 8) void layer_kernel(
    int in_mode,        // 0: read g_h0/g_h0T; 1/2: combine g_row/g_col[in_mode-1]
    int out_sel,
    const float* __restrict__ Wq_all, const float* __restrict__ Wk_all,
    const float* __restrict__ Wv_all, const float* __restrict__ Wo_all,
    const float* __restrict__ bo_all, int layer)
{
    const int slice = blockIdx.x;
    const int b     = blockIdx.y;
    const int axis  = blockIdx.z;
    const int t     = threadIdx.x;

    __shared__ __align__(16) float Xs[SS][DD];
    __shared__ __align__(16) float Qd[2][SS][8];    // [h][i][e*2+c] duplicated
    __shared__ __align__(16) float Kp[2][24][8];    // [h][j/2][e*2 + (j&1)]
    __shared__ __align__(16) float Vp[2][24][8];
    __shared__ __align__(16) float Os[SS][DD];
    __shared__ __align__(16) float Wsm[3][HDD][DD]; // Wq(*0.5), Wk, Wv
    __shared__ __align__(16) float Wos[DD][HDD];
    __shared__ __align__(16) float bos[DD];

    const int wofs = (layer * 2 + axis) * 64;

    // Weights -> smem (fold E^-0.5 = 0.5 into Wq)
    for (int k = t; k < 3 * 64; k += 96) {
        int m = k >> 6, r = k & 63;
        const float* src = (m == 0) ? Wq_all : (m == 1) ? Wk_all : Wv_all;
        float v = src[wofs + r];
        if (m == 0) v *= 0.5f;
        ((float*)Wsm)[k] = v;
    }
    if (t < 64) ((float*)Wos)[t] = Wo_all[wofs + t];
    else if (t < 64 + DD) bos[t - 64] = bo_all[(layer * 2 + axis) * DD + (t - 64)];

    // X slice -> smem with fused relu(row+col).  One half-token (float4)/thread.
    const int base = b * (SS * SS * DD);
    const int tok = t >> 1;
    {
        const int hf = (t & 1) * 4;
        const int own_addr   = base + (slice * SS + tok) * DD + hf;  // coalesced
        const int other_addr = base + (tok * SS + slice) * DD + hf;  // scattered
        if (in_mode == 0) {
            const float* own = (axis == 0) ? g_h0T : g_h0;
            *(float4*)&Xs[tok][hf] = *(const float4*)&own[own_addr];
        } else {
            const float* own   = (axis == 0) ? g_row[in_mode - 1] : g_col[in_mode - 1];
            const float* other = (axis == 0) ? g_col[in_mode - 1] : g_row[in_mode - 1];
            float4 rv = *(const float4*)&own[own_addr];
            float4 cv = *(const float4*)&other[other_addr];
            rv.x = fmaxf(rv.x + cv.x, 0.f);
            rv.y = fmaxf(rv.y + cv.y, 0.f);
            rv.z = fmaxf(rv.z + cv.z, 0.f);
            rv.w = fmaxf(rv.w + cv.w, 0.f);
            *(float4*)&Xs[tok][hf] = rv;
        }
    }
    __syncthreads();

    // Q,K,V projections: thread <-> (tok, head-quad).  X row loaded ONCE.
    {
        const int hq = t & 1;                       // head = hq
        const float4 xa = ((const float4*)Xs[tok])[0];
        const float4 xb = ((const float4*)Xs[tok])[1];
#pragma unroll
        for (int m = 0; m < 3; m++) {
            float v[4];
#pragma unroll
            for (int e = 0; e < 4; e++) {
                const float4* wr = (const float4*)Wsm[m][hq * 4 + e];
                float4 wa = wr[0], wb = wr[1];
                float2 acc = mul2(mk2(xa.x, xa.y), mk2(wa.x, wa.y));
                acc = fma2(mk2(xa.z, xa.w), mk2(wa.z, wa.w), acc);
                acc = fma2(mk2(xb.x, xb.y), mk2(wb.x, wb.y), acc);
                acc = fma2(mk2(xb.z, xb.w), mk2(wb.z, wb.w), acc);
                v[e] = acc.x + acc.y;
            }
            if (m == 0) {                           // Q duplicated, 2x STS.128
                *(float4*)&Qd[hq][tok][0] = make_float4(v[0], v[0], v[1], v[1]);
                *(float4*)&Qd[hq][tok][4] = make_float4(v[2], v[2], v[3], v[3]);
            } else if (m == 1) {                    // K pair-interleaved
#pragma unroll
                for (int e = 0; e < 4; e++) Kp[hq][tok >> 1][e * 2 + (tok & 1)] = v[e];
            } else {                                // V pair-interleaved
#pragma unroll
                for (int e = 0; e < 4; e++) Vp[hq][tok >> 1][e * 2 + (tok & 1)] = v[e];
            }
        }
    }
    __syncthreads();

    // Attention core: 2 keys per FFMA2 everywhere (unchanged).
    {
        const int h = t / SS;
        const int i = t - h * SS;
        const float2* qp = (const float2*)Qd[h][i];
        const float2 q0 = qp[0], q1 = qp[1], q2 = qp[2], q3 = qp[3];

        float2 a2[24];
        float mx = -1e30f;
#pragma unroll
        for (int jp = 0; jp < 24; jp++) {
            const float4* kp = (const float4*)Kp[h][jp];
            float4 k01 = kp[0], k23 = kp[1];
            float2 acc = mul2(q0, mk2(k01.x, k01.y));
            acc = fma2(q1, mk2(k01.z, k01.w), acc);
            acc = fma2(q2, mk2(k23.x, k23.y), acc);
            acc = fma2(q3, mk2(k23.z, k23.w), acc);
            a2[jp] = acc;
            mx = fmaxf(mx, fmaxf(acc.x, acc.y));
        }

        const float L2E = 1.4426950408889634f;
        const float2 l2 = mk2(L2E, L2E);
        const float nb  = -mx * L2E;
        const float2 nb2 = mk2(nb, nb);
        float s = 0.f;
#pragma unroll
        for (int jp = 0; jp < 24; jp++) {
            float2 e = fma2(a2[jp], l2, nb2);
            e.x = ex2f(e.x);
            e.y = ex2f(e.y);
            a2[jp] = e;
            s += e.x + e.y;
        }
        const float inv = 1.f / s;

        float2 o0 = mk2(0.f, 0.f), o1 = o0, o2 = o0, o3 = o0;
#pragma unroll
        for (int jp = 0; jp < 24; jp++) {
            const float4* vp = (const float4*)Vp[h][jp];
            float4 v01 = vp[0], v23 = vp[1];
            float2 a = a2[jp];
            o0 = fma2(a, mk2(v01.x, v01.y), o0);
            o1 = fma2(a, mk2(v01.z, v01.w), o1);
            o2 = fma2(a, mk2(v23.x, v23.y), o2);
            o3 = fma2(a, mk2(v23.z, v23.w), o3);
        }
        Os[i][h * 4 + 0] = (o0.x + o0.y) * inv;
        Os[i][h * 4 + 1] = (o1.x + o1.y) * inv;
        Os[i][h * 4 + 2] = (o2.x + o2.y) * inv;
        Os[i][h * 4 + 3] = (o3.x + o3.y) * inv;
    }
    __syncthreads();

    // Output projection: thread <-> (tok, d-quad); ONE coalesced STG.128/thread.
    {
        const int dq = t & 1;
        const float4 oa = ((const float4*)Os[tok])[0];
        const float4 ob = ((const float4*)Os[tok])[1];
        const float4 bq = *(const float4*)&bos[dq * 4];
        float v[4];
#pragma unroll
        for (int e = 0; e < 4; e++) {
            const float4* wr = (const float4*)Wos[dq * 4 + e];
            float4 wa = wr[0], wb = wr[1];
            float2 acc = mul2(mk2(oa.x, oa.y), mk2(wa.x, wa.y));
            acc = fma2(mk2(oa.z, oa.w), mk2(wa.z, wa.w), acc);
            acc = fma2(mk2(ob.x, ob.y), mk2(wb.x, wb.y), acc);
            acc = fma2(mk2(ob.z, ob.w), mk2(wb.z, wb.w), acc);
            v[e] = acc.x + acc.y;
        }
        float* outbuf = (axis == 0) ? g_row[out_sel] : g_col[out_sel];  // own layout
        float4 r4 = make_float4(v[0] + bq.x, v[1] + bq.y, v[2] + bq.z, v[3] + bq.w);
        *(float4*)&outbuf[base + (slice * SS + tok) * DD + dq * 4] = r4;
    }
}

// ---------------------------------------------------------------------------
// Classifier.  g_col coalesced; g_row read through its transposed layout.
// ---------------------------------------------------------------------------
__global__ __launch_bounds__(256) void cls_kernel(
    const float* __restrict__ cls_w, const float* __restrict__ cls_b,
    float* __restrict__ out, int sel)
{
    const int b = blockIdx.x;
    const int t = threadIdx.x;
    const float* rT = g_row[sel];   // [b][j][i][d]
    const float* c  = g_col[sel];   // [b][i][j][d]
    const int base = b * SS * SS * DD;

    float part[NCLS];
#pragma unroll
    for (int cc = 0; cc < NCLS; cc++) part[cc] = 0.f;

    for (int k = t; k < SS * SS; k += 256) {
        const int i = k / SS, j = k - i * SS;
        const float4* pr = (const float4*)&rT[base + (j * SS + i) * 8];
        const float4* pc = (const float4*)&c[base + k * 8];
        float4 r0 = pr[0], r1 = pr[1], c0 = pc[0], c1 = pc[1];
        float m = fmaxf(fmaxf(fmaxf(r0.x + c0.x, r0.y + c0.y), fmaxf(r0.z + c0.z, r0.w + c0.w)),
                        fmaxf(fmaxf(r1.x + c1.x, r1.y + c1.y), fmaxf(r1.z + c1.z, r1.w + c1.w)));
        m = fmaxf(m, 0.f);
#pragma unroll
        for (int cc = 0; cc < NCLS; cc++)
            part[cc] = fmaf(m, cls_w[cc * (SS * SS) + k], part[cc]);
    }

    __shared__ float red[NCLS][256];
#pragma unroll
    for (int cc = 0; cc < NCLS; cc++) red[cc][t] = part[cc];
    __syncthreads();
    for (int off = 128; off > 0; off >>= 1) {
        if (t < off) {
#pragma unroll
            for (int cc = 0; cc < NCLS; cc++) red[cc][t] += red[cc][t + off];
        }
        __syncthreads();
    }
    if (t == 0) {
        float lg[NCLS];
        float mx = -1e30f;
#pragma unroll
        for (int cc = 0; cc < NCLS; cc++) {
            lg[cc] = red[cc][0] + cls_b[cc];
            mx = fmaxf(mx, lg[cc]);
        }
        float s = 0.f;
#pragma unroll
        for (int cc = 0; cc < NCLS; cc++) { lg[cc] = __expf(lg[cc] - mx); s += lg[cc]; }
        float inv = 1.f / s;
#pragma unroll
        for (int cc = 0; cc < NCLS; cc++) out[b * NCLS + cc] = lg[cc] * inv;
    }
}

// ---------------------------------------------------------------------------
extern "C" void kernel_launch(void* const* d_in, const int* in_sizes, int n_in,
                              void* d_out, int out_size)
{
    (void)in_sizes; (void)n_in; (void)out_size;
    const float* x       = (const float*)d_in[0];
    const float* enc_w   = (const float*)d_in[1];
    const float* enc_b   = (const float*)d_in[2];
    const float* pos_row = (const float*)d_in[3];
    const float* pos_col = (const float*)d_in[4];
    const float* Wq      = (const float*)d_in[5];
    const float* Wk      = (const float*)d_in[6];
    const float* Wv      = (const float*)d_in[7];
    const float* Wo      = (const float*)d_in[8];
    const float* bo      = (const float*)d_in[9];
    const float* cls_w   = (const float*)d_in[10];
    const float* cls_b   = (const float*)d_in[11];

    encoder_kernel<<<(BB * SS * SS + 255) / 256, 256>>>(x, enc_w, enc_b, pos_row, pos_col);

    dim3 grid(SS, BB, 2);
    for (int l = 0; l < LL; l++) {
        int in_mode = (l == 0) ? 0 : 1 + ((l - 1) & 1);
        int out_sel = l & 1;
        layer_kernel<<<grid, 96>>>(in_mode, out_sel, Wq, Wk, Wv, Wo, bo, l);
    }

    cls_kernel<<<BB, 256>>>(cls_w, cls_b, (float*)d_out, (LL - 1) & 1);
}

// round 12
// speedup vs baseline: 1.1387x; 1.1387x over previous
#include <cuda_runtime.h>

#define BB 128
#define SS 48
#define DD 8
#define HDD 8
#define LL 8
#define NCLS 7
#define NTOT (BB*SS*SS*DD)   // 2,359,296 floats = 9.4 MB

// Static scratch. Layout convention:
//   g_h0  [b][i][j][d]
//   g_h0T [b][j][i][d]   (transposed copy: axis-0 reads coalesced)
//   g_col [b][i][j][d]   (axis-1 outputs, own-layout)
//   g_row [b][j][i][d]   (axis-0 outputs, TRANSPOSED own-layout)
__device__ float g_h0[NTOT];
__device__ float g_h0T[NTOT];
__device__ float g_row[2][NTOT];
__device__ float g_col[2][NTOT];

// ---------------- f32x2 packed-math helpers (Blackwell) ----------------
__device__ __forceinline__ float2 mk2(float a, float b) { return make_float2(a, b); }

__device__ __forceinline__ float2 mul2(float2 a, float2 b) {
    float2 r;
    asm("mul.rn.f32x2 %0, %1, %2;"
        : "=l"(reinterpret_cast<unsigned long long&>(r))
        : "l"(reinterpret_cast<const unsigned long long&>(a)),
          "l"(reinterpret_cast<const unsigned long long&>(b)));
    return r;
}
__device__ __forceinline__ float2 fma2(float2 a, float2 b, float2 c) {
    float2 r;
    asm("fma.rn.f32x2 %0, %1, %2, %3;"
        : "=l"(reinterpret_cast<unsigned long long&>(r))
        : "l"(reinterpret_cast<const unsigned long long&>(a)),
          "l"(reinterpret_cast<const unsigned long long&>(b)),
          "l"(reinterpret_cast<const unsigned long long&>(c)));
    return r;
}
__device__ __forceinline__ float ex2f(float x) {
    float r; asm("ex2.approx.f32 %0, %1;" : "=f"(r) : "f"(x)); return r;
}

// 8-float dot via f32x2, inputs as two float4 pairs.
__device__ __forceinline__ float dot8(float4 xa, float4 xb, float4 wa, float4 wb) {
    float2 acc = mul2(mk2(xa.x, xa.y), mk2(wa.x, wa.y));
    acc = fma2(mk2(xa.z, xa.w), mk2(wa.z, wa.w), acc);
    acc = fma2(mk2(xb.x, xb.y), mk2(wb.x, wb.y), acc);
    acc = fma2(mk2(xb.z, xb.w), mk2(wb.z, wb.w), acc);
    return acc.x + acc.y;
}

// ---------------------------------------------------------------------------
// Encoder: writes both layouts so layer 0 reads coalesced on both axes.
// ---------------------------------------------------------------------------
__global__ __launch_bounds__(256) void encoder_kernel(
    const float* __restrict__ x,
    const float* __restrict__ enc_w,
    const float* __restrict__ enc_b,
    const float* __restrict__ pos_row,
    const float* __restrict__ pos_col)
{
    int idx = blockIdx.x * blockDim.x + threadIdx.x;   // (b,i,j)
    if (idx >= BB * SS * SS) return;
    int j = idx % SS;
    int i = (idx / SS) % SS;
    int b = idx / (SS * SS);
    float xv = x[idx];
    float out[8];
#pragma unroll
    for (int d = 0; d < 8; d++) {
        float v = fmaxf(fmaf(xv, enc_w[d], enc_b[d]), 0.f);
        out[d] = v + pos_row[i * DD + d] + pos_col[j * DD + d];
    }
    float4 lo = make_float4(out[0], out[1], out[2], out[3]);
    float4 hi = make_float4(out[4], out[5], out[6], out[7]);
    float4* dst = (float4*)&g_h0[(size_t)idx * 8];
    dst[0] = lo; dst[1] = hi;
    float4* dstT = (float4*)&g_h0T[((size_t)(b * SS + j) * SS + i) * 8];
    dstT[0] = lo; dstT[1] = hi;
}

// ---------------------------------------------------------------------------
// One axial self-attention block.  blockIdx = (slice, batch, axis).
// Own-layout GMEM accesses are fully coalesced; SMEM mapping uses fixed
// hd = t&7 per thread (broadcast-group loads, <=2-way-conflict stores).
// ---------------------------------------------------------------------------
__global__ __launch_bounds__(96, 8) void layer_kernel(
    int in_mode,        // 0: read g_h0/g_h0T; 1/2: combine g_row/g_col[in_mode-1]
    int out_sel,
    const float* __restrict__ Wq_all, const float* __restrict__ Wk_all,
    const float* __restrict__ Wv_all, const float* __restrict__ Wo_all,
    const float* __restrict__ bo_all, int layer)
{
    const int slice = blockIdx.x;
    const int b     = blockIdx.y;
    const int axis  = blockIdx.z;
    const int t     = threadIdx.x;

    __shared__ __align__(16) float Xs[SS][DD];
    __shared__ __align__(16) float Qd[2][SS][8];    // [h][i][e*2+c] duplicated
    __shared__ __align__(16) float Kp[2][24][8];    // [h][j/2][e*2 + (j&1)]
    __shared__ __align__(16) float Vp[2][24][8];
    __shared__ __align__(16) float Os[SS][DD];
    __shared__ __align__(16) float Wsm[3][HDD][DD]; // Wq(*0.5), Wk, Wv
    __shared__ __align__(16) float Wos[DD][HDD];
    __shared__ __align__(16) float bos[DD];

    const int wofs = (layer * 2 + axis) * 64;

    // Weights -> smem (fold E^-0.5 = 0.5 into Wq)
    for (int k = t; k < 3 * 64; k += 96) {
        int m = k >> 6, r = k & 63;
        const float* src = (m == 0) ? Wq_all : (m == 1) ? Wk_all : Wv_all;
        float v = src[wofs + r];
        if (m == 0) v *= 0.5f;
        ((float*)Wsm)[k] = v;
    }
    if (t < 64) ((float*)Wos)[t] = Wo_all[wofs + t];
    else if (t < 64 + DD) bos[t - 64] = bo_all[(layer * 2 + axis) * DD + (t - 64)];

    // X slice -> smem with fused relu(row+col).  One float4 per thread.
    const int base = b * (SS * SS * DD);
    {
        const int tokX = t >> 1, hf = (t & 1) * 4;
        const int own_addr   = base + (slice * SS + tokX) * DD + hf;  // coalesced
        const int other_addr = base + (tokX * SS + slice) * DD + hf;  // scattered
        if (in_mode == 0) {
            const float* own = (axis == 0) ? g_h0T : g_h0;
            *(float4*)&Xs[tokX][hf] = *(const float4*)&own[own_addr];
        } else {
            const float* own   = (axis == 0) ? g_row[in_mode - 1] : g_col[in_mode - 1];
            const float* other = (axis == 0) ? g_col[in_mode - 1] : g_row[in_mode - 1];
            float4 rv = *(const float4*)&own[own_addr];
            float4 cv = *(const float4*)&other[other_addr];
            rv.x = fmaxf(rv.x + cv.x, 0.f);
            rv.y = fmaxf(rv.y + cv.y, 0.f);
            rv.z = fmaxf(rv.z + cv.z, 0.f);
            rv.w = fmaxf(rv.w + cv.w, 0.f);
            *(float4*)&Xs[tokX][hf] = rv;
        }
    }
    __syncthreads();

    const int hd = t & 7;           // fixed per thread
    const int g  = t >> 3;          // 0..11
    const int hh = hd >> 2, ee = hd & 3;

    // Q,K,V projections: W rows hoisted (loop-invariant), X row broadcast-loaded.
    {
        const float4 wqa = ((const float4*)Wsm[0][hd])[0], wqb = ((const float4*)Wsm[0][hd])[1];
        const float4 wka = ((const float4*)Wsm[1][hd])[0], wkb = ((const float4*)Wsm[1][hd])[1];
        const float4 wva = ((const float4*)Wsm[2][hd])[0], wvb = ((const float4*)Wsm[2][hd])[1];
#pragma unroll
        for (int it = 0; it < 4; it++) {
            const int tok = it * 12 + g;
            const float4 xa = ((const float4*)Xs[tok])[0];
            const float4 xb = ((const float4*)Xs[tok])[1];
            float qv = dot8(xa, xb, wqa, wqb);
            float kv = dot8(xa, xb, wka, wkb);
            float vv = dot8(xa, xb, wva, wvb);
            Qd[hh][tok][ee * 2]     = qv;
            Qd[hh][tok][ee * 2 + 1] = qv;
            Kp[hh][tok >> 1][ee * 2 + (tok & 1)] = kv;
            Vp[hh][tok >> 1][ee * 2 + (tok & 1)] = vv;
        }
    }
    __syncthreads();

    // Attention core: 2 keys per FFMA2 everywhere (broadcast LDS).
    {
        const int h = t / SS;
        const int i = t - h * SS;
        const float2* qp = (const float2*)Qd[h][i];
        const float2 q0 = qp[0], q1 = qp[1], q2 = qp[2], q3 = qp[3];

        float2 a2[24];
        float mx = -1e30f;
#pragma unroll
        for (int jp = 0; jp < 24; jp++) {
            const float4* kp = (const float4*)Kp[h][jp];
            float4 k01 = kp[0], k23 = kp[1];
            float2 acc = mul2(q0, mk2(k01.x, k01.y));
            acc = fma2(q1, mk2(k01.z, k01.w), acc);
            acc = fma2(q2, mk2(k23.x, k23.y), acc);
            acc = fma2(q3, mk2(k23.z, k23.w), acc);
            a2[jp] = acc;
            mx = fmaxf(mx, fmaxf(acc.x, acc.y));
        }

        const float L2E = 1.4426950408889634f;
        const float2 l2 = mk2(L2E, L2E);
        const float nb  = -mx * L2E;
        const float2 nb2 = mk2(nb, nb);
        float s = 0.f;
#pragma unroll
        for (int jp = 0; jp < 24; jp++) {
            float2 e = fma2(a2[jp], l2, nb2);
            e.x = ex2f(e.x);
            e.y = ex2f(e.y);
            a2[jp] = e;
            s += e.x + e.y;
        }
        const float inv = 1.f / s;

        float2 o0 = mk2(0.f, 0.f), o1 = o0, o2 = o0, o3 = o0;
#pragma unroll
        for (int jp = 0; jp < 24; jp++) {
            const float4* vp = (const float4*)Vp[h][jp];
            float4 v01 = vp[0], v23 = vp[1];
            float2 a = a2[jp];
            o0 = fma2(a, mk2(v01.x, v01.y), o0);
            o1 = fma2(a, mk2(v01.z, v01.w), o1);
            o2 = fma2(a, mk2(v23.x, v23.y), o2);
            o3 = fma2(a, mk2(v23.z, v23.w), o3);
        }
        Os[i][h * 4 + 0] = (o0.x + o0.y) * inv;
        Os[i][h * 4 + 1] = (o1.x + o1.y) * inv;
        Os[i][h * 4 + 2] = (o2.x + o2.y) * inv;
        Os[i][h * 4 + 3] = (o3.x + o3.y) * inv;
    }
    __syncthreads();

    // Output projection: fixed d = t&7; store address = base + slice*384 + it*96 + t
    // -> perfectly coalesced STG.32 into the own-layout array.
    {
        const float4 woa = ((const float4*)Wos[hd])[0], wob = ((const float4*)Wos[hd])[1];
        const float bias = bos[hd];
        float* outbuf = (axis == 0) ? g_row[out_sel] : g_col[out_sel];
        const int sbase = base + slice * (SS * DD);
#pragma unroll
        for (int it = 0; it < 4; it++) {
            const int tok = it * 12 + g;
            const float4 oa = ((const float4*)Os[tok])[0];
            const float4 ob = ((const float4*)Os[tok])[1];
            outbuf[sbase + it * 96 + t] = dot8(oa, ob, woa, wob) + bias;
        }
    }
}

// ---------------------------------------------------------------------------
// Classifier.  g_col coalesced; g_row read through its transposed layout.
// ---------------------------------------------------------------------------
__global__ __launch_bounds__(256) void cls_kernel(
    const float* __restrict__ cls_w, const float* __restrict__ cls_b,
    float* __restrict__ out, int sel)
{
    const int b = blockIdx.x;
    const int t = threadIdx.x;
    const float* rT = g_row[sel];   // [b][j][i][d]
    const float* c  = g_col[sel];   // [b][i][j][d]
    const int base = b * SS * SS * DD;

    float part[NCLS];
#pragma unroll
    for (int cc = 0; cc < NCLS; cc++) part[cc] = 0.f;

    for (int k = t; k < SS * SS; k += 256) {
        const int i = k / SS, j = k - i * SS;
        const float4* pr = (const float4*)&rT[base + (j * SS + i) * 8];
        const float4* pc = (const float4*)&c[base + k * 8];
        float4 r0 = pr[0], r1 = pr[1], c0 = pc[0], c1 = pc[1];
        float m = fmaxf(fmaxf(fmaxf(r0.x + c0.x, r0.y + c0.y), fmaxf(r0.z + c0.z, r0.w + c0.w)),
                        fmaxf(fmaxf(r1.x + c1.x, r1.y + c1.y), fmaxf(r1.z + c1.z, r1.w + c1.w)));
        m = fmaxf(m, 0.f);
#pragma unroll
        for (int cc = 0; cc < NCLS; cc++)
            part[cc] = fmaf(m, cls_w[cc * (SS * SS) + k], part[cc]);
    }

    __shared__ float red[NCLS][256];
#pragma unroll
    for (int cc = 0; cc < NCLS; cc++) red[cc][t] = part[cc];
    __syncthreads();
    for (int off = 128; off > 0; off >>= 1) {
        if (t < off) {
#pragma unroll
            for (int cc = 0; cc < NCLS; cc++) red[cc][t] += red[cc][t + off];
        }
        __syncthreads();
    }
    if (t == 0) {
        float lg[NCLS];
        float mx = -1e30f;
#pragma unroll
        for (int cc = 0; cc < NCLS; cc++) {
            lg[cc] = red[cc][0] + cls_b[cc];
            mx = fmaxf(mx, lg[cc]);
        }
        float s = 0.f;
#pragma unroll
        for (int cc = 0; cc < NCLS; cc++) { lg[cc] = __expf(lg[cc] - mx); s += lg[cc]; }
        float inv = 1.f / s;
#pragma unroll
        for (int cc = 0; cc < NCLS; cc++) out[b * NCLS + cc] = lg[cc] * inv;
    }
}

// ---------------------------------------------------------------------------
extern "C" void kernel_launch(void* const* d_in, const int* in_sizes, int n_in,
                              void* d_out, int out_size)
{
    (void)in_sizes; (void)n_in; (void)out_size;
    const float* x       = (const float*)d_in[0];
    const float* enc_w   = (const float*)d_in[1];
    const float* enc_b   = (const float*)d_in[2];
    const float* pos_row = (const float*)d_in[3];
    const float* pos_col = (const float*)d_in[4];
    const float* Wq      = (const float*)d_in[5];
    const float* Wk      = (const float*)d_in[6];
    const float* Wv      = (const float*)d_in[7];
    const float* Wo      = (const float*)d_in[8];
    const float* bo      = (const float*)d_in[9];
    const float* cls_w   = (const float*)d_in[10];
    const float* cls_b   = (const float*)d_in[11];

    encoder_kernel<<<(BB * SS * SS + 255) / 256, 256>>>(x, enc_w, enc_b, pos_row, pos_col);

    dim3 grid(SS, BB, 2);
    for (int l = 0; l < LL; l++) {
        int in_mode = (l == 0) ? 0 : 1 + ((l - 1) & 1);
        int out_sel = l & 1;
        layer_kernel<<<grid, 96>>>(in_mode, out_sel, Wq, Wk, Wv, Wo, bo, l);
    }

    cls_kernel<<<BB, 256>>>(cls_w, cls_b, (float*)d_out, (LL - 1) & 1);
}

// round 14
// speedup vs baseline: 1.2132x; 1.0654x over previous
#include <cuda_runtime.h>

#define BB 128
#define SS 48
#define DD 8
#define HDD 8
#define LL 8
#define NCLS 7
#define NTOT (BB*SS*SS*DD)   // 2,359,296 floats = 9.4 MB

// Static scratch. Layout convention:
//   g_h0  [b][i][j][d]
//   g_h0T [b][j][i][d]   (transposed copy: axis-0 reads coalesced)
//   g_col [b][i][j][d]   (axis-1 outputs, own-layout)
//   g_row [b][j][i][d]   (axis-0 outputs, TRANSPOSED own-layout)
__device__ float g_h0[NTOT];
__device__ float g_h0T[NTOT];
__device__ float g_row[2][NTOT];
__device__ float g_col[2][NTOT];

// ---------------- f32x2 packed-math helpers (Blackwell) ----------------
__device__ __forceinline__ float2 mk2(float a, float b) { return make_float2(a, b); }

__device__ __forceinline__ float2 mul2(float2 a, float2 b) {
    float2 r;
    asm("mul.rn.f32x2 %0, %1, %2;"
        : "=l"(reinterpret_cast<unsigned long long&>(r))
        : "l"(reinterpret_cast<const unsigned long long&>(a)),
          "l"(reinterpret_cast<const unsigned long long&>(b)));
    return r;
}
__device__ __forceinline__ float2 fma2(float2 a, float2 b, float2 c) {
    float2 r;
    asm("fma.rn.f32x2 %0, %1, %2, %3;"
        : "=l"(reinterpret_cast<unsigned long long&>(r))
        : "l"(reinterpret_cast<const unsigned long long&>(a)),
          "l"(reinterpret_cast<const unsigned long long&>(b)),
          "l"(reinterpret_cast<const unsigned long long&>(c)));
    return r;
}
__device__ __forceinline__ float ex2f(float x) {
    float r; asm("ex2.approx.f32 %0, %1;" : "=f"(r) : "f"(x)); return r;
}

// 8-float dot via f32x2, inputs as two float4 pairs.
__device__ __forceinline__ float dot8(float4 xa, float4 xb, float4 wa, float4 wb) {
    float2 acc = mul2(mk2(xa.x, xa.y), mk2(wa.x, wa.y));
    acc = fma2(mk2(xa.z, xa.w), mk2(wa.z, wa.w), acc);
    acc = fma2(mk2(xb.x, xb.y), mk2(wb.x, wb.y), acc);
    acc = fma2(mk2(xb.z, xb.w), mk2(wb.z, wb.w), acc);
    return acc.x + acc.y;
}

// ---------------------------------------------------------------------------
// Encoder: writes both layouts so layer 0 reads coalesced on both axes.
// ---------------------------------------------------------------------------
__global__ __launch_bounds__(256) void encoder_kernel(
    const float* __restrict__ x,
    const float* __restrict__ enc_w,
    const float* __restrict__ enc_b,
    const float* __restrict__ pos_row,
    const float* __restrict__ pos_col)
{
    int idx = blockIdx.x * blockDim.x + threadIdx.x;   // (b,i,j)
    if (idx >= BB * SS * SS) return;
    int j = idx % SS;
    int i = (idx / SS) % SS;
    int b = idx / (SS * SS);
    float xv = x[idx];
    float out[8];
#pragma unroll
    for (int d = 0; d < 8; d++) {
        float v = fmaxf(fmaf(xv, enc_w[d], enc_b[d]), 0.f);
        out[d] = v + pos_row[i * DD + d] + pos_col[j * DD + d];
    }
    float4 lo = make_float4(out[0], out[1], out[2], out[3]);
    float4 hi = make_float4(out[4], out[5], out[6], out[7]);
    float4* dst = (float4*)&g_h0[(size_t)idx * 8];
    dst[0] = lo; dst[1] = hi;
    float4* dstT = (float4*)&g_h0T[((size_t)(b * SS + j) * SS + i) * 8];
    dstT[0] = lo; dstT[1] = hi;
}

// ---------------------------------------------------------------------------
// One axial self-attention block.  blockIdx = (slice, batch, axis).
// SMEM layouts padded/transposed for conflict-free access:
//   QdT[2][4][50]  : Q transposed (lane i -> bank i, conflict-free core loads)
//   Kp/Vp[2][24][12]: pair-interleaved, 48B rows (aligned LDS.128 broadcast)
//   Os[48][10]     : 40B rows (core scalar stores 2-way, epilogue LDS.64)
// ---------------------------------------------------------------------------
__global__ __launch_bounds__(96, 8) void layer_kernel(
    int in_mode,        // 0: read g_h0/g_h0T; 1/2: combine g_row/g_col[in_mode-1]
    int out_sel,
    const float* __restrict__ Wq_all, const float* __restrict__ Wk_all,
    const float* __restrict__ Wv_all, const float* __restrict__ Wo_all,
    const float* __restrict__ bo_all, int layer)
{
    const int slice = blockIdx.x;
    const int b     = blockIdx.y;
    const int axis  = blockIdx.z;
    const int t     = threadIdx.x;

    __shared__ __align__(16) float Xs[SS][DD];
    __shared__ __align__(16) float QdT[2][4][50];   // [h][e][i] (padded 48->50)
    __shared__ __align__(16) float Kp[2][24][12];   // [h][j/2][e*2 + (j&1)] pad 8->12
    __shared__ __align__(16) float Vp[2][24][12];
    __shared__ __align__(16) float Os[SS][10];      // [i][h*4+e] pad 8->10
    __shared__ __align__(16) float Wsm[3][HDD][DD]; // Wq(*0.5), Wk, Wv
    __shared__ __align__(16) float Wos[DD][HDD];
    __shared__ __align__(16) float bos[DD];

    const int wofs = (layer * 2 + axis) * 64;

    // Weights -> smem (fold E^-0.5 = 0.5 into Wq)
    for (int k = t; k < 3 * 64; k += 96) {
        int m = k >> 6, r = k & 63;
        const float* src = (m == 0) ? Wq_all : (m == 1) ? Wk_all : Wv_all;
        float v = src[wofs + r];
        if (m == 0) v *= 0.5f;
        ((float*)Wsm)[k] = v;
    }
    if (t < 64) ((float*)Wos)[t] = Wo_all[wofs + t];
    else if (t < 64 + DD) bos[t - 64] = bo_all[(layer * 2 + axis) * DD + (t - 64)];

    // X slice -> smem with fused relu(row+col).  One float4 per thread.
    const int base = b * (SS * SS * DD);
    {
        const int tokX = t >> 1, hf = (t & 1) * 4;
        const int own_addr   = base + (slice * SS + tokX) * DD + hf;  // coalesced
        const int other_addr = base + (tokX * SS + slice) * DD + hf;  // scattered
        if (in_mode == 0) {
            const float* own = (axis == 0) ? g_h0T : g_h0;
            *(float4*)&Xs[tokX][hf] = *(const float4*)&own[own_addr];
        } else {
            const float* own   = (axis == 0) ? g_row[in_mode - 1] : g_col[in_mode - 1];
            const float* other = (axis == 0) ? g_col[in_mode - 1] : g_row[in_mode - 1];
            float4 rv = *(const float4*)&own[own_addr];
            float4 cv = *(const float4*)&other[other_addr];
            rv.x = fmaxf(rv.x + cv.x, 0.f);
            rv.y = fmaxf(rv.y + cv.y, 0.f);
            rv.z = fmaxf(rv.z + cv.z, 0.f);
            rv.w = fmaxf(rv.w + cv.w, 0.f);
            *(float4*)&Xs[tokX][hf] = rv;
        }
    }
    __syncthreads();

    const int hd = t & 7;           // fixed per thread
    const int g  = t >> 3;          // 0..11
    const int hh = hd >> 2, ee = hd & 3;

    // Q,K,V projections: W rows hoisted (loop-invariant), X row broadcast-loaded.
    {
        const float4 wqa = ((const float4*)Wsm[0][hd])[0], wqb = ((const float4*)Wsm[0][hd])[1];
        const float4 wka = ((const float4*)Wsm[1][hd])[0], wkb = ((const float4*)Wsm[1][hd])[1];
        const float4 wva = ((const float4*)Wsm[2][hd])[0], wvb = ((const float4*)Wsm[2][hd])[1];
#pragma unroll
        for (int it = 0; it < 4; it++) {
            const int tok = it * 12 + g;
            const float4 xa = ((const float4*)Xs[tok])[0];
            const float4 xb = ((const float4*)Xs[tok])[1];
            float qv = dot8(xa, xb, wqa, wqb);
            float kv = dot8(xa, xb, wka, wkb);
            float vv = dot8(xa, xb, wva, wvb);
            QdT[hh][ee][tok] = qv;                          // transposed, single store
            Kp[hh][tok >> 1][ee * 2 + (tok & 1)] = kv;
            Vp[hh][tok >> 1][ee * 2 + (tok & 1)] = vv;
        }
    }
    __syncthreads();

    // Attention core: 2 keys per FFMA2; Q loaded conflict-free (lane i -> bank i).
    {
        const int h = t / SS;
        const int i = t - h * SS;
        const float q0s = QdT[h][0][i], q1s = QdT[h][1][i];
        const float q2s = QdT[h][2][i], q3s = QdT[h][3][i];
        const float2 q0 = mk2(q0s, q0s), q1 = mk2(q1s, q1s);
        const float2 q2 = mk2(q2s, q2s), q3 = mk2(q3s, q3s);

        float2 a2[24];
        float mx = -1e30f;
#pragma unroll
        for (int jp = 0; jp < 24; jp++) {
            const float4* kp = (const float4*)Kp[h][jp];
            float4 k01 = kp[0], k23 = kp[1];
            float2 acc = mul2(q0, mk2(k01.x, k01.y));
            acc = fma2(q1, mk2(k01.z, k01.w), acc);
            acc = fma2(q2, mk2(k23.x, k23.y), acc);
            acc = fma2(q3, mk2(k23.z, k23.w), acc);
            a2[jp] = acc;
            mx = fmaxf(mx, fmaxf(acc.x, acc.y));
        }

        const float L2E = 1.4426950408889634f;
        const float2 l2  = mk2(L2E, L2E);
        const float nb   = -mx * L2E;
        const float2 nb2 = mk2(nb, nb);
        const float2 one2 = mk2(1.f, 1.f);
        float2 s2 = mk2(0.f, 0.f);
#pragma unroll
        for (int jp = 0; jp < 24; jp++) {
            float2 e = fma2(a2[jp], l2, nb2);
            e.x = ex2f(e.x);
            e.y = ex2f(e.y);
            a2[jp] = e;
            s2 = fma2(e, one2, s2);
        }
        const float inv = 1.f / (s2.x + s2.y);

        float2 o0 = mk2(0.f, 0.f), o1 = o0, o2 = o0, o3 = o0;
#pragma unroll
        for (int jp = 0; jp < 24; jp++) {
            const float4* vp = (const float4*)Vp[h][jp];
            float4 v01 = vp[0], v23 = vp[1];
            float2 a = a2[jp];
            o0 = fma2(a, mk2(v01.x, v01.y), o0);
            o1 = fma2(a, mk2(v01.z, v01.w), o1);
            o2 = fma2(a, mk2(v23.x, v23.y), o2);
            o3 = fma2(a, mk2(v23.z, v23.w), o3);
        }
        Os[i][h * 4 + 0] = (o0.x + o0.y) * inv;
        Os[i][h * 4 + 1] = (o1.x + o1.y) * inv;
        Os[i][h * 4 + 2] = (o2.x + o2.y) * inv;
        Os[i][h * 4 + 3] = (o3.x + o3.y) * inv;
    }
    __syncthreads();

    // Output projection: fixed d = t&7; O rows via aligned LDS.64 (40B offsets);
    // store address = base + slice*384 + it*96 + t -> perfectly coalesced STG.32.
    {
        const float4 woa = ((const float4*)Wos[hd])[0], wob = ((const float4*)Wos[hd])[1];
        const float bias = bos[hd];
        float* outbuf = (axis == 0) ? g_row[out_sel] : g_col[out_sel];
        const int sbase = base + slice * (SS * DD);
#pragma unroll
        for (int it = 0; it < 4; it++) {
            const int tok = it * 12 + g;
            const float2* op = (const float2*)Os[tok];      // 40B row offset: 8B-aligned
            float2 p0 = op[0], p1 = op[1], p2 = op[2], p3 = op[3];
            float4 oa = make_float4(p0.x, p0.y, p1.x, p1.y);
            float4 ob = make_float4(p2.x, p2.y, p3.x, p3.y);
            outbuf[sbase + it * 96 + t] = dot8(oa, ob, woa, wob) + bias;
        }
    }
}

// ---------------------------------------------------------------------------
// Classifier.  g_col coalesced; g_row read through its transposed layout.
// ---------------------------------------------------------------------------
__global__ __launch_bounds__(256) void cls_kernel(
    const float* __restrict__ cls_w, const float* __restrict__ cls_b,
    float* __restrict__ out, int sel)
{
    const int b = blockIdx.x;
    const int t = threadIdx.x;
    const float* rT = g_row[sel];   // [b][j][i][d]
    const float* c  = g_col[sel];   // [b][i][j][d]
    const int base = b * SS * SS * DD;

    float part[NCLS];
#pragma unroll
    for (int cc = 0; cc < NCLS; cc++) part[cc] = 0.f;

    for (int k = t; k < SS * SS; k += 256) {
        const int i = k / SS, j = k - i * SS;
        const float4* pr = (const float4*)&rT[base + (j * SS + i) * 8];
        const float4* pc = (const float4*)&c[base + k * 8];
        float4 r0 = pr[0], r1 = pr[1], c0 = pc[0], c1 = pc[1];
        float m = fmaxf(fmaxf(fmaxf(r0.x + c0.x, r0.y + c0.y), fmaxf(r0.z + c0.z, r0.w + c0.w)),
                        fmaxf(fmaxf(r1.x + c1.x, r1.y + c1.y), fmaxf(r1.z + c1.z, r1.w + c1.w)));
        m = fmaxf(m, 0.f);
#pragma unroll
        for (int cc = 0; cc < NCLS; cc++)
            part[cc] = fmaf(m, cls_w[cc * (SS * SS) + k], part[cc]);
    }

    __shared__ float red[NCLS][256];
#pragma unroll
    for (int cc = 0; cc < NCLS; cc++) red[cc][t] = part[cc];
    __syncthreads();
    for (int off = 128; off > 0; off >>= 1) {
        if (t < off) {
#pragma unroll
            for (int cc = 0; cc < NCLS; cc++) red[cc][t] += red[cc][t + off];
        }
        __syncthreads();
    }
    if (t == 0) {
        float lg[NCLS];
        float mx = -1e30f;
#pragma unroll
        for (int cc = 0; cc < NCLS; cc++) {
            lg[cc] = red[cc][0] + cls_b[cc];
            mx = fmaxf(mx, lg[cc]);
        }
        float s = 0.f;
#pragma unroll
        for (int cc = 0; cc < NCLS; cc++) { lg[cc] = __expf(lg[cc] - mx); s += lg[cc]; }
        float inv = 1.f / s;
#pragma unroll
        for (int cc = 0; cc < NCLS; cc++) out[b * NCLS + cc] = lg[cc] * inv;
    }
}

// ---------------------------------------------------------------------------
extern "C" void kernel_launch(void* const* d_in, const int* in_sizes, int n_in,
                              void* d_out, int out_size)
{
    (void)in_sizes; (void)n_in; (void)out_size;
    const float* x       = (const float*)d_in[0];
    const float* enc_w   = (const float*)d_in[1];
    const float* enc_b   = (const float*)d_in[2];
    const float* pos_row = (const float*)d_in[3];
    const float* pos_col = (const float*)d_in[4];
    const float* Wq      = (const float*)d_in[5];
    const float* Wk      = (const float*)d_in[6];
    const float* Wv      = (const float*)d_in[7];
    const float* Wo      = (const float*)d_in[8];
    const float* bo      = (const float*)d_in[9];
    const float* cls_w   = (const float*)d_in[10];
    const float* cls_b   = (const float*)d_in[11];

    encoder_kernel<<<(BB * SS * SS + 255) / 256, 256>>>(x, enc_w, enc_b, pos_row, pos_col);

    dim3 grid(SS, BB, 2);
    for (int l = 0; l < LL; l++) {
        int in_mode = (l == 0) ? 0 : 1 + ((l - 1) & 1);
        int out_sel = l & 1;
        layer_kernel<<<grid, 96>>>(in_mode, out_sel, Wq, Wk, Wv, Wo, bo, l);
    }

    cls_kernel<<<BB, 256>>>(cls_w, cls_b, (float*)d_out, (LL - 1) & 1);
}

// round 15
// speedup vs baseline: 1.2637x; 1.0416x over previous
#include <cuda_runtime.h>

#define BB 128
#define SS 48
#define DD 8
#define HDD 8
#define LL 8
#define NCLS 7
#define NTOT (BB*SS*SS*DD)   // 2,359,296 floats = 9.4 MB

// Static scratch. Layout convention:
//   g_h0  [b][i][j][d]
//   g_h0T [b][j][i][d]   (transposed copy: axis-0 reads coalesced)
//   g_col [b][i][j][d]   (axis-1 outputs, own-layout)
//   g_row [b][j][i][d]   (axis-0 outputs, TRANSPOSED own-layout)
__device__ float g_h0[NTOT];
__device__ float g_h0T[NTOT];
__device__ float g_row[2][NTOT];
__device__ float g_col[2][NTOT];

// ---------------- f32x2 packed-math helpers (Blackwell) ----------------
__device__ __forceinline__ float2 mk2(float a, float b) { return make_float2(a, b); }

__device__ __forceinline__ float2 mul2(float2 a, float2 b) {
    float2 r;
    asm("mul.rn.f32x2 %0, %1, %2;"
        : "=l"(reinterpret_cast<unsigned long long&>(r))
        : "l"(reinterpret_cast<const unsigned long long&>(a)),
          "l"(reinterpret_cast<const unsigned long long&>(b)));
    return r;
}
__device__ __forceinline__ float2 fma2(float2 a, float2 b, float2 c) {
    float2 r;
    asm("fma.rn.f32x2 %0, %1, %2, %3;"
        : "=l"(reinterpret_cast<unsigned long long&>(r))
        : "l"(reinterpret_cast<const unsigned long long&>(a)),
          "l"(reinterpret_cast<const unsigned long long&>(b)),
          "l"(reinterpret_cast<const unsigned long long&>(c)));
    return r;
}
__device__ __forceinline__ float ex2f(float x) {
    float r; asm("ex2.approx.f32 %0, %1;" : "=f"(r) : "f"(x)); return r;
}

// 8-float dot via f32x2, inputs as two float4 pairs.
__device__ __forceinline__ float dot8(float4 xa, float4 xb, float4 wa, float4 wb) {
    float2 acc = mul2(mk2(xa.x, xa.y), mk2(wa.x, wa.y));
    acc = fma2(mk2(xa.z, xa.w), mk2(wa.z, wa.w), acc);
    acc = fma2(mk2(xb.x, xb.y), mk2(wb.x, wb.y), acc);
    acc = fma2(mk2(xb.z, xb.w), mk2(wb.z, wb.w), acc);
    return acc.x + acc.y;
}

// ---------------------------------------------------------------------------
// Encoder: writes both layouts so layer 0 reads coalesced on both axes.
// ---------------------------------------------------------------------------
__global__ __launch_bounds__(256) void encoder_kernel(
    const float* __restrict__ x,
    const float* __restrict__ enc_w,
    const float* __restrict__ enc_b,
    const float* __restrict__ pos_row,
    const float* __restrict__ pos_col)
{
    int idx = blockIdx.x * blockDim.x + threadIdx.x;   // (b,i,j)
    if (idx >= BB * SS * SS) return;
    int j = idx % SS;
    int i = (idx / SS) % SS;
    int b = idx / (SS * SS);
    float xv = x[idx];
    float out[8];
#pragma unroll
    for (int d = 0; d < 8; d++) {
        float v = fmaxf(fmaf(xv, enc_w[d], enc_b[d]), 0.f);
        out[d] = v + pos_row[i * DD + d] + pos_col[j * DD + d];
    }
    float4 lo = make_float4(out[0], out[1], out[2], out[3]);
    float4 hi = make_float4(out[4], out[5], out[6], out[7]);
    float4* dst = (float4*)&g_h0[(size_t)idx * 8];
    dst[0] = lo; dst[1] = hi;
    float4* dstT = (float4*)&g_h0T[((size_t)(b * SS + j) * SS + i) * 8];
    dstT[0] = lo; dstT[1] = hi;
}

// ---------------------------------------------------------------------------
// Axial self-attention, TWO slices per block.  blockIdx = (slice_pair, b, axis).
// 96 threads.  Core: thread t -> group = t/24 -> (sl = group>>1, h = group&1),
// iq = t%24, handling queries i0=iq and i1=iq+24 -> each K/V row loaded once
// serves two queries (halves the core broadcast-LDS stream).
// Bank layout: Kp/Vp row-dim 25 -> group slab offsets {0,12,24,4} mod 32 banks
// (disjoint 16B ranges -> concurrent broadcasts coalesce); QdT inner dim 54 ->
// h-slab stride = 24 mod 32 -> scalar Q loads conflict-free.
// ---------------------------------------------------------------------------
__global__ __launch_bounds__(96, 4) void layer_kernel(
    int in_mode,        // 0: read g_h0/g_h0T; 1/2: combine g_row/g_col[in_mode-1]
    int out_sel,
    const float* __restrict__ Wq_all, const float* __restrict__ Wk_all,
    const float* __restrict__ Wv_all, const float* __restrict__ Wo_all,
    const float* __restrict__ bo_all, int layer)
{
    const int sp    = blockIdx.x;       // slice pair: slices 2sp, 2sp+1
    const int b     = blockIdx.y;
    const int axis  = blockIdx.z;
    const int t     = threadIdx.x;

    __shared__ __align__(16) float Xs[2][SS][DD];
    __shared__ __align__(16) float QdT[2][2][4][54];   // [sl][h][e][i] pad 48->54
    __shared__ __align__(16) float Kp[2][2][25][12];   // [sl][h][j/2][e*2+(j&1)]
    __shared__ __align__(16) float Vp[2][2][25][12];
    __shared__ __align__(16) float Os[2][SS][10];      // [sl][i][h*4+e] pad 8->10
    __shared__ __align__(16) float Wsm[3][HDD][DD];    // Wq(*0.5), Wk, Wv
    __shared__ __align__(16) float Wos[DD][HDD];
    __shared__ __align__(16) float bos[DD];

    const int wofs = (layer * 2 + axis) * 64;

    // Weights -> smem (fold E^-0.5 = 0.5 into Wq); amortized over 2 slices.
    for (int k = t; k < 3 * 64; k += 96) {
        int m = k >> 6, r = k & 63;
        const float* src = (m == 0) ? Wq_all : (m == 1) ? Wk_all : Wv_all;
        float v = src[wofs + r];
        if (m == 0) v *= 0.5f;
        ((float*)Wsm)[k] = v;
    }
    if (t < 64) ((float*)Wos)[t] = Wo_all[wofs + t];
    else if (t < 64 + DD) bos[t - 64] = bo_all[(layer * 2 + axis) * DD + (t - 64)];

    // X for both slices -> smem with fused relu(row+col).  2 float4 per thread.
    const int base = b * (SS * SS * DD);
#pragma unroll
    for (int k = t; k < 192; k += 96) {
        const int sl   = k / 96;
        const int rem  = k - sl * 96;
        const int tokX = rem >> 1, hf = (rem & 1) * 4;
        const int sg   = 2 * sp + sl;
        const int own_addr   = base + (sg * SS + tokX) * DD + hf;  // coalesced
        const int other_addr = base + (tokX * SS + sg) * DD + hf;  // scattered
        if (in_mode == 0) {
            const float* own = (axis == 0) ? g_h0T : g_h0;
            *(float4*)&Xs[sl][tokX][hf] = *(const float4*)&own[own_addr];
        } else {
            const float* own   = (axis == 0) ? g_row[in_mode - 1] : g_col[in_mode - 1];
            const float* other = (axis == 0) ? g_col[in_mode - 1] : g_row[in_mode - 1];
            float4 rv = *(const float4*)&own[own_addr];
            float4 cv = *(const float4*)&other[other_addr];
            rv.x = fmaxf(rv.x + cv.x, 0.f);
            rv.y = fmaxf(rv.y + cv.y, 0.f);
            rv.z = fmaxf(rv.z + cv.z, 0.f);
            rv.w = fmaxf(rv.w + cv.w, 0.f);
            *(float4*)&Xs[sl][tokX][hf] = rv;
        }
    }
    __syncthreads();

    const int hd = t & 7;           // fixed per thread
    const int g  = t >> 3;          // 0..11
    const int hh = hd >> 2, ee = hd & 3;

    // Q,K,V projections over 96 tokens (2 slices): W rows hoisted, X broadcast.
    {
        const float4 wqa = ((const float4*)Wsm[0][hd])[0], wqb = ((const float4*)Wsm[0][hd])[1];
        const float4 wka = ((const float4*)Wsm[1][hd])[0], wkb = ((const float4*)Wsm[1][hd])[1];
        const float4 wva = ((const float4*)Wsm[2][hd])[0], wvb = ((const float4*)Wsm[2][hd])[1];
#pragma unroll
        for (int it = 0; it < 8; it++) {
            const int tk = it * 12 + g;        // 0..95
            const int sl = tk >= SS;
            const int lt = tk - sl * SS;
            const float4 xa = ((const float4*)Xs[sl][lt])[0];
            const float4 xb = ((const float4*)Xs[sl][lt])[1];
            float qv = dot8(xa, xb, wqa, wqb);
            float kv = dot8(xa, xb, wka, wkb);
            float vv = dot8(xa, xb, wva, wvb);
            QdT[sl][hh][ee][lt] = qv;
            Kp[sl][hh][lt >> 1][ee * 2 + (lt & 1)] = kv;
            Vp[sl][hh][lt >> 1][ee * 2 + (lt & 1)] = vv;
        }
    }
    __syncthreads();

    // Attention core: 2 queries/thread share every K/V load.
    {
        const int group = t / 24;           // 0..3
        const int sl = group >> 1;
        const int h  = group & 1;
        const int iq = t - group * 24;
        const int i0 = iq, i1 = iq + 24;

        const float q0a = QdT[sl][h][0][i0], q1a = QdT[sl][h][1][i0];
        const float q2a = QdT[sl][h][2][i0], q3a = QdT[sl][h][3][i0];
        const float q0b = QdT[sl][h][0][i1], q1b = QdT[sl][h][1][i1];
        const float q2b = QdT[sl][h][2][i1], q3b = QdT[sl][h][3][i1];
        const float2 qa0 = mk2(q0a, q0a), qa1 = mk2(q1a, q1a), qa2 = mk2(q2a, q2a), qa3 = mk2(q3a, q3a);
        const float2 qb0 = mk2(q0b, q0b), qb1 = mk2(q1b, q1b), qb2 = mk2(q2b, q2b), qb3 = mk2(q3b, q3b);

        float2 aA[24], aB[24];
        float mxA = -1e30f, mxB = -1e30f;
#pragma unroll
        for (int jp = 0; jp < 24; jp++) {
            const float4* kp = (const float4*)Kp[sl][h][jp];
            float4 k01 = kp[0], k23 = kp[1];
            float2 e01 = mk2(k01.x, k01.y), e23 = mk2(k01.z, k01.w);
            float2 e45 = mk2(k23.x, k23.y), e67 = mk2(k23.z, k23.w);
            float2 dA = mul2(qa0, e01);
            dA = fma2(qa1, e23, dA);
            dA = fma2(qa2, e45, dA);
            dA = fma2(qa3, e67, dA);
            float2 dB = mul2(qb0, e01);
            dB = fma2(qb1, e23, dB);
            dB = fma2(qb2, e45, dB);
            dB = fma2(qb3, e67, dB);
            aA[jp] = dA;
            aB[jp] = dB;
            mxA = fmaxf(mxA, fmaxf(dA.x, dA.y));
            mxB = fmaxf(mxB, fmaxf(dB.x, dB.y));
        }

        const float L2E = 1.4426950408889634f;
        const float2 l2   = mk2(L2E, L2E);
        const float2 nbA  = mk2(-mxA * L2E, -mxA * L2E);
        const float2 nbB  = mk2(-mxB * L2E, -mxB * L2E);
        const float2 one2 = mk2(1.f, 1.f);
        float2 sA = mk2(0.f, 0.f), sB = mk2(0.f, 0.f);
#pragma unroll
        for (int jp = 0; jp < 24; jp++) {
            float2 eA = fma2(aA[jp], l2, nbA);
            float2 eB = fma2(aB[jp], l2, nbB);
            eA.x = ex2f(eA.x); eA.y = ex2f(eA.y);
            eB.x = ex2f(eB.x); eB.y = ex2f(eB.y);
            aA[jp] = eA; aB[jp] = eB;
            sA = fma2(eA, one2, sA);
            sB = fma2(eB, one2, sB);
        }
        const float invA = 1.f / (sA.x + sA.y);
        const float invB = 1.f / (sB.x + sB.y);

        float2 oA0 = mk2(0.f, 0.f), oA1 = oA0, oA2 = oA0, oA3 = oA0;
        float2 oB0 = oA0, oB1 = oA0, oB2 = oA0, oB3 = oA0;
#pragma unroll
        for (int jp = 0; jp < 24; jp++) {
            const float4* vp = (const float4*)Vp[sl][h][jp];
            float4 v01 = vp[0], v23 = vp[1];
            float2 w01 = mk2(v01.x, v01.y), w23 = mk2(v01.z, v01.w);
            float2 w45 = mk2(v23.x, v23.y), w67 = mk2(v23.z, v23.w);
            float2 eA = aA[jp], eB = aB[jp];
            oA0 = fma2(eA, w01, oA0);
            oA1 = fma2(eA, w23, oA1);
            oA2 = fma2(eA, w45, oA2);
            oA3 = fma2(eA, w67, oA3);
            oB0 = fma2(eB, w01, oB0);
            oB1 = fma2(eB, w23, oB1);
            oB2 = fma2(eB, w45, oB2);
            oB3 = fma2(eB, w67, oB3);
        }
        Os[sl][i0][h * 4 + 0] = (oA0.x + oA0.y) * invA;
        Os[sl][i0][h * 4 + 1] = (oA1.x + oA1.y) * invA;
        Os[sl][i0][h * 4 + 2] = (oA2.x + oA2.y) * invA;
        Os[sl][i0][h * 4 + 3] = (oA3.x + oA3.y) * invA;
        Os[sl][i1][h * 4 + 0] = (oB0.x + oB0.y) * invB;
        Os[sl][i1][h * 4 + 1] = (oB1.x + oB1.y) * invB;
        Os[sl][i1][h * 4 + 2] = (oB2.x + oB2.y) * invB;
        Os[sl][i1][h * 4 + 3] = (oB3.x + oB3.y) * invB;
    }
    __syncthreads();

    // Output projection over 96 tokens; coalesced STG.32 (addr = ... + it*96 + t).
    {
        const float4 woa = ((const float4*)Wos[hd])[0], wob = ((const float4*)Wos[hd])[1];
        const float bias = bos[hd];
        float* outbuf = (axis == 0) ? g_row[out_sel] : g_col[out_sel];
        const int sbase = base + (2 * sp) * (SS * DD);
#pragma unroll
        for (int it = 0; it < 8; it++) {
            const int tk = it * 12 + g;
            const int sl = tk >= SS;
            const int lt = tk - sl * SS;
            const float2* op = (const float2*)Os[sl][lt];   // 40B rows, 8B-aligned
            float2 p0 = op[0], p1 = op[1], p2 = op[2], p3 = op[3];
            float4 oa = make_float4(p0.x, p0.y, p1.x, p1.y);
            float4 ob = make_float4(p2.x, p2.y, p3.x, p3.y);
            outbuf[sbase + it * 96 + t] = dot8(oa, ob, woa, wob) + bias;
        }
    }
}

// ---------------------------------------------------------------------------
// Classifier.  g_col coalesced; g_row read through its transposed layout.
// ---------------------------------------------------------------------------
__global__ __launch_bounds__(256) void cls_kernel(
    const float* __restrict__ cls_w, const float* __restrict__ cls_b,
    float* __restrict__ out, int sel)
{
    const int b = blockIdx.x;
    const int t = threadIdx.x;
    const float* rT = g_row[sel];   // [b][j][i][d]
    const float* c  = g_col[sel];   // [b][i][j][d]
    const int base = b * SS * SS * DD;

    float part[NCLS];
#pragma unroll
    for (int cc = 0; cc < NCLS; cc++) part[cc] = 0.f;

    for (int k = t; k < SS * SS; k += 256) {
        const int i = k / SS, j = k - i * SS;
        const float4* pr = (const float4*)&rT[base + (j * SS + i) * 8];
        const float4* pc = (const float4*)&c[base + k * 8];
        float4 r0 = pr[0], r1 = pr[1], c0 = pc[0], c1 = pc[1];
        float m = fmaxf(fmaxf(fmaxf(r0.x + c0.x, r0.y + c0.y), fmaxf(r0.z + c0.z, r0.w + c0.w)),
                        fmaxf(fmaxf(r1.x + c1.x, r1.y + c1.y), fmaxf(r1.z + c1.z, r1.w + c1.w)));
        m = fmaxf(m, 0.f);
#pragma unroll
        for (int cc = 0; cc < NCLS; cc++)
            part[cc] = fmaf(m, cls_w[cc * (SS * SS) + k], part[cc]);
    }

    __shared__ float red[NCLS][256];
#pragma unroll
    for (int cc = 0; cc < NCLS; cc++) red[cc][t] = part[cc];
    __syncthreads();
    for (int off = 128; off > 0; off >>= 1) {
        if (t < off) {
#pragma unroll
            for (int cc = 0; cc < NCLS; cc++) red[cc][t] += red[cc][t + off];
        }
        __syncthreads();
    }
    if (t == 0) {
        float lg[NCLS];
        float mx = -1e30f;
#pragma unroll
        for (int cc = 0; cc < NCLS; cc++) {
            lg[cc] = red[cc][0] + cls_b[cc];
            mx = fmaxf(mx, lg[cc]);
        }
        float s = 0.f;
#pragma unroll
        for (int cc = 0; cc < NCLS; cc++) { lg[cc] = __expf(lg[cc] - mx); s += lg[cc]; }
        float inv = 1.f / s;
#pragma unroll
        for (int cc = 0; cc < NCLS; cc++) out[b * NCLS + cc] = lg[cc] * inv;
    }
}

// ---------------------------------------------------------------------------
extern "C" void kernel_launch(void* const* d_in, const int* in_sizes, int n_in,
                              void* d_out, int out_size)
{
    (void)in_sizes; (void)n_in; (void)out_size;
    const float* x       = (const float*)d_in[0];
    const float* enc_w   = (const float*)d_in[1];
    const float* enc_b   = (const float*)d_in[2];
    const float* pos_row = (const float*)d_in[3];
    const float* pos_col = (const float*)d_in[4];
    const float* Wq      = (const float*)d_in[5];
    const float* Wk      = (const float*)d_in[6];
    const float* Wv      = (const float*)d_in[7];
    const float* Wo      = (const float*)d_in[8];
    const float* bo      = (const float*)d_in[9];
    const float* cls_w   = (const float*)d_in[10];
    const float* cls_b   = (const float*)d_in[11];

    encoder_kernel<<<(BB * SS * SS + 255) / 256, 256>>>(x, enc_w, enc_b, pos_row, pos_col);

    dim3 grid(SS / 2, BB, 2);
    for (int l = 0; l < LL; l++) {
        int in_mode = (l == 0) ? 0 : 1 + ((l - 1) & 1);
        int out_sel = l & 1;
        layer_kernel<<<grid, 96>>>(in_mode, out_sel, Wq, Wk, Wv, Wo, bo, l);
    }

    cls_kernel<<<BB, 256>>>(cls_w, cls_b, (float*)d_out, (LL - 1) & 1);
}